// round 16
// baseline (speedup 1.0000x reference)
#include <cuda_runtime.h>
#include <cstdint>

#define Bq 2
#define Cq 64
#define Vq 180
#define Dq 384
#define Wq 1024
#define NCHUNK 4
#define IDX_PER_CHUNK (Bq*Vq*Wq/NCHUNK)     // 92160
#define TILE_PER_CHUNK (Bq*Vq*Wq*2/128/NCHUNK) // 1440

// ---------------- scratch (device globals) ----------------
__device__ __align__(16) float g_feat[(size_t)Bq*Vq*Dq*96];
__device__ __align__(16) float g_X[(size_t)Bq*Vq*Wq*2*64];
__device__ __align__(16) float g_pred[Bq*Vq*Wq*2];
__device__ __align__(16) float g_coef[Bq*Vq*Wq*2];
__device__ float g_resc[Bq*Vq*Wq];
__device__ __align__(16) unsigned long long g_cwd[96*576];
__device__ float g_cb[96];
__device__ __align__(16) float g_W0t[256*64];
__device__ __align__(16) float g_W1c[8*256*32];
__device__ float g_cph[32];

// ---------------- helpers ----------------
__device__ __forceinline__ uint32_t smem_u32(const void* p) {
  uint32_t a;
  asm("{ .reg .u64 t; cvta.to.shared.u64 t, %1; cvt.u32.u64 %0, t; }" : "=r"(a) : "l"(p));
  return a;
}
__device__ __forceinline__ float tf32r(float x) {
  uint32_t r;
  asm("cvt.rna.tf32.f32 %0, %1;" : "=r"(r) : "f"(x));
  return __uint_as_float(r);
}
__device__ __forceinline__ unsigned long long pack2(float lo, float hi) {
  unsigned long long d;
  asm("mov.b64 %0, {%1, %2};" : "=l"(d) : "f"(lo), "f"(hi));
  return d;
}
__device__ __forceinline__ unsigned long long ffma2(unsigned long long a,
                                                    unsigned long long b,
                                                    unsigned long long c) {
  unsigned long long d;
  asm("fma.rn.f32x2 %0, %1, %2, %3;" : "=l"(d) : "l"(a), "l"(b), "l"(c));
  return d;
}
__device__ __forceinline__ float2 unpack2(unsigned long long u) {
  float2 f;
  asm("mov.b64 {%0,%1}, %2;" : "=f"(f.x), "=f"(f.y) : "l"(u));
  return f;
}
#define CPA16(d, s) asm volatile("cp.async.ca.shared.global [%0], [%1], 16;" :: "r"(d), "l"(s) : "memory")
#define CPCOMMIT()  asm volatile("cp.async.commit_group;" ::: "memory")
#define CPWAIT(n)   asm volatile("cp.async.wait_group %0;" :: "n"(n) : "memory")

__device__ __forceinline__ void mma_tf32(float* d, const uint32_t* a, const uint32_t* b) {
  asm volatile("mma.sync.aligned.m16n8k8.row.col.f32.tf32.tf32.f32 "
               "{%0,%1,%2,%3}, {%4,%5,%6,%7}, {%8,%9}, {%0,%1,%2,%3};"
               : "+f"(d[0]), "+f"(d[1]), "+f"(d[2]), "+f"(d[3])
               : "r"(a[0]), "r"(a[1]), "r"(a[2]), "r"(a[3]), "r"(b[0]), "r"(b[1]));
}
__device__ __forceinline__ void ldmx4(uint32_t* r, uint32_t addr) {
  asm volatile("ldmatrix.sync.aligned.m8n8.x4.shared.b16 {%0,%1,%2,%3}, [%4];"
               : "=r"(r[0]), "=r"(r[1]), "=r"(r[2]), "=r"(r[3]) : "r"(addr));
}
__device__ __forceinline__ void ldmx2(uint32_t* r, uint32_t addr) {
  asm volatile("ldmatrix.sync.aligned.m8n8.x2.shared.b16 {%0,%1}, [%2];"
               : "=r"(r[0]), "=r"(r[1]) : "r"(addr));
}

// ---------------- prep ----------------
__global__ void prep_kernel(const float* __restrict__ coef_w, const float* __restrict__ coef_b,
                            const float* __restrict__ freq_w, const float* __restrict__ freq_b,
                            const float* __restrict__ phase_w, const void* __restrict__ scale_raw,
                            const float* __restrict__ w0, const float* __restrict__ w1) {
  int t = blockIdx.x * blockDim.x + threadIdx.x;
  if (t < 96*576) {
    int oc = t / 576, j = t % 576;
    float w;
    if (oc < 64) w = coef_w[oc*576 + j];
    else {
      int p = oc - 64;
      w = freq_w[(2*p)*576 + j] + freq_w[(2*p+1)*576 + j];
    }
    g_cwd[t] = pack2(w, w);
  }
  if (t < 96) g_cb[t] = (t < 64) ? coef_b[t] : (freq_b[2*(t-64)] + freq_b[2*(t-64)+1]);
  if (t < 64*256) {
    int k = t >> 8, h = t & 255;
    g_W0t[h*64 + k] = tf32r(w0[k*256 + h]);
  }
  {
    int k = t >> 8, h = t & 255;
    int c = k >> 5, kk = k & 31;
    g_W1c[((size_t)c*256 + h)*32 + kk] = tf32r(w1[k*256 + h]);
  }
  if (t < 32) {
    int raw = *(const int*)scale_raw;
    float sc;
    if (raw > 0 && raw < 1000000) sc = (float)raw;
    else {
      float f = __int_as_float(raw);
      sc = (f > 0.01f && f < 1.0e6f) ? f : 2.0f;
    }
    g_cph[t] = (2.0f / sc) * phase_w[t];
  }
}

// ---------------- conv3x3, 96 out ch, zero pad, f32x2, 8oc x 8pos ----------------
__global__ void __launch_bounds__(96) conv_kernel(const float* __restrict__ sino) {
  extern __shared__ float s_in[];
  const int b = blockIdx.z, v = blockIdx.y, d0 = blockIdx.x * 64;
  const int tid = threadIdx.x;
  for (int i = tid; i < 64*198; i += 96) {
    int c = i / 198, rem = i % 198, r = rem / 66, col = rem % 66;
    int gv = v - 1 + r, gd = d0 - 1 + col;
    float val = 0.f;
    if (gv >= 0 && gv < Vq && gd >= 0 && gd < Dq)
      val = sino[(((size_t)b*Cq + c)*Vq + gv)*Dq + gd];
    s_in[i] = val;
  }
  __syncthreads();
  const int pos0 = (tid & 7) * 8;
  const int oc0 = (tid >> 3) * 8;
  unsigned long long acc2[8][4];
#pragma unroll
  for (int i = 0; i < 8; i++)
#pragma unroll
    for (int pj = 0; pj < 4; pj++) acc2[i][pj] = 0ull;
  for (int c = 0; c < 64; c++) {
#pragma unroll
    for (int ky = 0; ky < 3; ky++) {
      float in[10];
      int base = c*198 + ky*66 + pos0;
#pragma unroll
      for (int q = 0; q < 10; q++) in[q] = s_in[base + q];
      unsigned long long P[9];
#pragma unroll
      for (int m = 0; m < 9; m++) P[m] = pack2(in[m], in[m+1]);
#pragma unroll
      for (int i = 0; i < 8; i++) {
        const unsigned long long* wdp = g_cwd + (size_t)(oc0+i)*576 + c*9 + ky*3;
        unsigned long long w0v = wdp[0], w1v = wdp[1], w2v = wdp[2];
#pragma unroll
        for (int pj = 0; pj < 4; pj++) {
          acc2[i][pj] = ffma2(w0v, P[2*pj],     acc2[i][pj]);
          acc2[i][pj] = ffma2(w1v, P[2*pj + 1], acc2[i][pj]);
          acc2[i][pj] = ffma2(w2v, P[2*pj + 2], acc2[i][pj]);
        }
      }
    }
  }
  size_t outbase = (((size_t)b*Vq + v)*Dq + d0 + pos0) * 96;
#pragma unroll
  for (int i = 0; i < 8; i++) {
    float bb = g_cb[oc0+i];
#pragma unroll
    for (int pj = 0; pj < 4; pj++) {
      float2 vv = unpack2(acc2[i][pj]);
      g_feat[outbase + (size_t)(2*pj)*96 + oc0 + i]   = vv.x + bb;
      g_feat[outbase + (size_t)(2*pj+1)*96 + oc0 + i] = vv.y + bb;
    }
  }
}

// ---------------- featurize (chunked) ----------------
__global__ void __launch_bounds__(256) feat_kernel(const float* __restrict__ sino,
                                                   const float* __restrict__ grid,
                                                   const float* __restrict__ sq,
                                                   int idxBase) {
  int idx = idxBase + blockIdx.x * blockDim.x + threadIdx.x;
  const int b = idx / (Vq*Wq);
  const float gx = grid[(size_t)idx*2], gy = grid[(size_t)idx*2 + 1];
  const float sqv = sq[idx] * 10000.f;

  float ix = fminf(fmaxf(((gx + 1.f)*Dq - 1.f)*0.5f, 0.f), (float)(Dq-1));
  float iy = fminf(fmaxf(((gy + 1.f)*Vq - 1.f)*0.5f, 0.f), (float)(Vq-1));
  float x0f = floorf(ix), y0f = floorf(iy);
  float wx = ix - x0f, wy = iy - y0f;
  int x0 = (int)x0f, y0 = (int)y0f;
  int x1 = min(x0 + 1, Dq-1), y1 = min(y0 + 1, Vq-1);
  const float* mid = sino + ((size_t)b*Cq + 32)*Vq*Dq;
  float v00 = mid[(size_t)y0*Dq + x0], v01 = mid[(size_t)y0*Dq + x1];
  float v10 = mid[(size_t)y1*Dq + x0], v11 = mid[(size_t)y1*Dq + x1];
  float bp = (v00*(1.f-wx) + v01*wx)*(1.f-wy) + (v10*(1.f-wx) + v11*wx)*wy;
  g_resc[idx] = bp * sqv;

  const int yi = min(max((int)rintf(iy), 0), Vq-1);
  float cph[32];
#pragma unroll
  for (int p = 0; p < 32; p++) cph[p] = g_cph[p];

  const float shmag = 1.0f/(float)Dq + 1e-6f;
  float len[2];
#pragma unroll 1
  for (int si = 0; si < 2; si++) {
    float sh = si ? shmag : -shmag;
    float ixs = fminf(fmaxf(((gx + sh + 1.f)*Dq - 1.f)*0.5f, 0.f), (float)(Dq-1));
    int xi = min(max((int)rintf(ixs), 0), Dq-1);
    float qc = (2.f*(float)xi + 1.f)/(float)Dq - 1.f;
    float rel = (gx - qc)*(float)Dq;
    len[si] = fabsf(rel) + 1e-4f;
    const float4* f4 = (const float4*)(g_feat + (((size_t)b*Vq + yi)*Dq + xi)*96);
    float xw[64];
#pragma unroll
    for (int p0 = 0; p0 < 32; p0 += 8) {
      float4 cl0 = f4[p0/4],      cl1 = f4[p0/4 + 1];
      float4 ch0 = f4[8 + p0/4],  ch1 = f4[9 + p0/4];
      float4 fs0 = f4[16 + p0/4], fs1 = f4[17 + p0/4];
      float clo[8] = {cl0.x,cl0.y,cl0.z,cl0.w, cl1.x,cl1.y,cl1.z,cl1.w};
      float chi[8] = {ch0.x,ch0.y,ch0.z,ch0.w, ch1.x,ch1.y,ch1.z,ch1.w};
      float fsv[8] = {fs0.x,fs0.y,fs0.z,fs0.w, fs1.x,fs1.y,fs1.z,fs1.w};
#pragma unroll
      for (int j = 0; j < 8; j++) {
        float fr = fmaf(rel, fsv[j], cph[p0 + j]);
        float sn, cs;
        sincospif(fr, &sn, &cs);
        xw[p0 + j]      = tf32r(clo[j]*cs);
        xw[32 + p0 + j] = tf32r(chi[j]*sn);
      }
    }
    size_t pt = (size_t)idx*2 + si;
    float4* dst = (float4*)(g_X + pt*64);
#pragma unroll
    for (int gq = 0; gq < 16; gq++)
      dst[gq] = make_float4(xw[4*gq], xw[4*gq+1], xw[4*gq+2], xw[4*gq+3]);
  }
  float tot = len[0] + len[1];
  g_coef[idx*2]     = sqv * len[1] / tot;
  g_coef[idx*2 + 1] = sqv * len[0] / tot;
}

// ---------------- MLP (chunked, tf32 + ldmatrix, proven core) ----------------
#define PXT 68
#define PW  68
#define PW1 36
#define H1P 260
#define OFF_W0  8704
#define OFF_BUF 33280
#define BUFSZ   9216
#define SMEM_MLP ((OFF_BUF + 2*BUFSZ) * 4)

__global__ void __launch_bounds__(512, 1) mlp_mma_kernel(const float* __restrict__ b0,
                                                         const float* __restrict__ b1,
                                                         const float* __restrict__ w2,
                                                         const float* __restrict__ b2,
                                                         int tileBase) {
  extern __shared__ float smem[];
  const uint32_t sbase = smem_u32(smem);
  const size_t tile = (size_t)tileBase + blockIdx.x;
  const int tid = threadIdx.x;
  const int wid = tid >> 5, lane = tid & 31;
  const int g = lane >> 2, tig = lane & 3;
  const int mg = wid & 3;
  const int m0w = mg * 64, n0w = (wid >> 2) * 32;
  const int lr16 = lane & 15;
  const int lr8  = lane & 7;
  const int acol = ((lane >> 4) & 1) * 4;
  const int bcol = ((lane >> 3) & 1) * 4;

  {
    const float* gX = g_X + tile * 8192;
    for (int i = tid; i < 2048; i += 512) {
      uint32_t d = sbase + (uint32_t)(((i >> 4)*PXT + (i & 15)*4) * 4);
      CPA16(d, gX + i*4);
    }
    for (int i = tid; i < 4096; i += 512) {
      uint32_t d = sbase + (uint32_t)((OFF_W0 + (i >> 4)*PW + (i & 15)*4) * 4);
      CPA16(d, g_W0t + (i >> 4)*64 + (i & 15)*4);
    }
    CPCOMMIT();
    for (int i = tid; i < 2048; i += 512) {
      uint32_t d = sbase + (uint32_t)((OFF_BUF + (i >> 3)*PW1 + (i & 7)*4) * 4);
      CPA16(d, g_W1c + (i >> 3)*32 + (i & 7)*4);
    }
    CPCOMMIT();
    for (int i = tid; i < 2048; i += 512) {
      uint32_t d = sbase + (uint32_t)((OFF_BUF + BUFSZ + (i >> 3)*PW1 + (i & 7)*4) * 4);
      CPA16(d, g_W1c + 8192 + (i >> 3)*32 + (i & 7)*4);
    }
    CPCOMMIT();
  }
  CPWAIT(2);
  __syncthreads();

  float acc0[4][4][4];
#pragma unroll
  for (int mt = 0; mt < 4; mt++)
#pragma unroll
    for (int nt = 0; nt < 4; nt++)
#pragma unroll
      for (int r = 0; r < 4; r++) acc0[mt][nt][r] = 0.f;
  {
    const uint32_t aBase = sbase + (uint32_t)((OFF_W0 + (m0w + lr16)*PW + acol) * 4);
    const uint32_t bBase = sbase + (uint32_t)(((n0w + lr8)*PXT + bcol) * 4);
#pragma unroll
    for (int ks = 0; ks < 8; ks++) {
      const uint32_t koff = (uint32_t)(ks * 32);
      uint32_t Af[4][4], Bf[4][2];
#pragma unroll
      for (int mt = 0; mt < 4; mt++) ldmx4(Af[mt], aBase + (uint32_t)(mt*16*PW*4) + koff);
#pragma unroll
      for (int nt = 0; nt < 4; nt++) ldmx2(Bf[nt], bBase + (uint32_t)(nt*8*PXT*4) + koff);
#pragma unroll
      for (int mt = 0; mt < 4; mt++)
#pragma unroll
        for (int nt = 0; nt < 4; nt++)
          mma_tf32(acc0[mt][nt], Af[mt], Bf[nt]);
    }
  }
  __syncthreads();

#pragma unroll
  for (int mt = 0; mt < 4; mt++) {
    int h_a = m0w + mt*16 + g, h_b = h_a + 8;
    float ba = b0[h_a], bbv = b0[h_b];
#pragma unroll
    for (int nt = 0; nt < 4; nt++) {
      int col = n0w + nt*8 + 2*tig;
      smem[col*H1P + h_a]       = tf32r(fmaxf(acc0[mt][nt][0] + ba, 0.f));
      smem[(col + 1)*H1P + h_a] = tf32r(fmaxf(acc0[mt][nt][1] + ba, 0.f));
      smem[col*H1P + h_b]       = tf32r(fmaxf(acc0[mt][nt][2] + bbv, 0.f));
      smem[(col + 1)*H1P + h_b] = tf32r(fmaxf(acc0[mt][nt][3] + bbv, 0.f));
    }
  }
  CPWAIT(1);
  __syncthreads();

  float acc1[4][4][4];
#pragma unroll
  for (int mt = 0; mt < 4; mt++)
#pragma unroll
    for (int nt = 0; nt < 4; nt++)
#pragma unroll
      for (int r = 0; r < 4; r++) acc1[mt][nt][r] = 0.f;

  const uint32_t bBase1 = sbase + (uint32_t)(((n0w + lr8)*H1P + bcol) * 4);
#pragma unroll 1
  for (int c = 0; c < 8; c++) {
    const int buf = OFF_BUF + (c & 1)*BUFSZ;
    const uint32_t aBase1 = sbase + (uint32_t)((buf + (m0w + lr16)*PW1 + acol) * 4);
    const uint32_t bChunk = bBase1 + (uint32_t)(c*32*4);
#pragma unroll
    for (int ks = 0; ks < 4; ks++) {
      const uint32_t koff = (uint32_t)(ks * 32);
      uint32_t Af[4][4], Bf[4][2];
#pragma unroll
      for (int mt = 0; mt < 4; mt++) ldmx4(Af[mt], aBase1 + (uint32_t)(mt*16*PW1*4) + koff);
#pragma unroll
      for (int nt = 0; nt < 4; nt++) ldmx2(Bf[nt], bChunk + (uint32_t)(nt*8*H1P*4) + koff);
#pragma unroll
      for (int mt = 0; mt < 4; mt++)
#pragma unroll
        for (int nt = 0; nt < 4; nt++)
          mma_tf32(acc1[mt][nt], Af[mt], Bf[nt]);
    }
    __syncthreads();
    if (c + 2 < 8) {
      const float* src = g_W1c + (size_t)(c + 2)*8192;
      for (int i = tid; i < 2048; i += 512) {
        uint32_t d = sbase + (uint32_t)((buf + (i >> 3)*PW1 + (i & 7)*4) * 4);
        CPA16(d, src + (i >> 3)*32 + (i & 7)*4);
      }
      CPCOMMIT();
      CPWAIT(1);
    } else {
      CPWAIT(0);
    }
    __syncthreads();
  }

  float pc[4][2];
#pragma unroll
  for (int nt = 0; nt < 4; nt++) { pc[nt][0] = 0.f; pc[nt][1] = 0.f; }
#pragma unroll
  for (int mt = 0; mt < 4; mt++) {
    int h_a = m0w + mt*16 + g, h_b = h_a + 8;
    float b1a = b1[h_a], w2a = w2[h_a];
    float b1b = b1[h_b], w2b = w2[h_b];
#pragma unroll
    for (int nt = 0; nt < 4; nt++) {
      pc[nt][0] += fmaxf(acc1[mt][nt][0] + b1a, 0.f)*w2a + fmaxf(acc1[mt][nt][2] + b1b, 0.f)*w2b;
      pc[nt][1] += fmaxf(acc1[mt][nt][1] + b1a, 0.f)*w2a + fmaxf(acc1[mt][nt][3] + b1b, 0.f)*w2b;
    }
  }
#pragma unroll
  for (int nt = 0; nt < 4; nt++) {
    int col = n0w + nt*8 + 2*tig;
    smem[OFF_BUF + col*33 + mg*8 + g]       = pc[nt][0];
    smem[OFF_BUF + (col + 1)*33 + mg*8 + g] = pc[nt][1];
  }
  __syncthreads();
  if (tid < 128) {
    float s = b2[0];
#pragma unroll
    for (int j = 0; j < 32; j++) s += smem[OFF_BUF + tid*33 + j];
    g_pred[tile*128 + tid] = s;
  }
}

// ---------------- final reduce: one warp per output pixel ----------------
__global__ void __launch_bounds__(256) reduce_kernel(float* __restrict__ out) {
  int o = blockIdx.x * 8 + (threadIdx.x >> 5);
  int lane = threadIdx.x & 31;
  int b = o >> 10, w = o & 1023;
  float s = 0.f;
  for (int v = lane; v < Vq; v += 32) {
    size_t idx = ((size_t)b*Vq + v)*Wq + w;
    float2 pr = *(const float2*)&g_pred[idx*2];
    float2 cf = *(const float2*)&g_coef[idx*2];
    s += g_resc[idx] + pr.x*cf.x + pr.y*cf.y;
  }
#pragma unroll
  for (int m = 16; m; m >>= 1) s += __shfl_xor_sync(0xFFFFFFFFu, s, m);
  if (lane == 0) out[o] = s;
}

extern "C" void kernel_launch(void* const* d_in, const int* in_sizes, int n_in,
                              void* d_out, int out_size) {
  const float* sino   = (const float*)d_in[0];
  const float* grid   = (const float*)d_in[1];
  const float* sq     = (const float*)d_in[2];
  const void*  scale  = d_in[3];
  const float* coef_w = (const float*)d_in[4];
  const float* coef_b = (const float*)d_in[5];
  const float* freq_w = (const float*)d_in[6];
  const float* freq_b = (const float*)d_in[7];
  const float* phase_w= (const float*)d_in[8];
  const float* w0     = (const float*)d_in[9];
  const float* b0     = (const float*)d_in[10];
  const float* w1     = (const float*)d_in[11];
  const float* b1     = (const float*)d_in[12];
  const float* w2     = (const float*)d_in[13];
  const float* b2     = (const float*)d_in[14];
  float* out = (float*)d_out;

  static int configured = 0;
  static cudaStream_t s1, s2;
  static cudaEvent_t eConv, eA, eB;
  if (!configured) {
    cudaFuncSetAttribute(mlp_mma_kernel, cudaFuncAttributeMaxDynamicSharedMemorySize, SMEM_MLP);
    cudaFuncSetAttribute(conv_kernel,    cudaFuncAttributeMaxDynamicSharedMemorySize, 50688);
    cudaStreamCreateWithFlags(&s1, cudaStreamNonBlocking);
    cudaStreamCreateWithFlags(&s2, cudaStreamNonBlocking);
    cudaEventCreateWithFlags(&eConv, cudaEventDisableTiming);
    cudaEventCreateWithFlags(&eA, cudaEventDisableTiming);
    cudaEventCreateWithFlags(&eB, cudaEventDisableTiming);
    configured = 1;
  }

  prep_kernel<<<256, 256>>>(coef_w, coef_b, freq_w, freq_b, phase_w, scale, w0, w1);
  conv_kernel<<<dim3(Dq/64, Vq, Bq), 96, 50688>>>(sino);
  cudaEventRecord(eConv, 0);
  cudaStreamWaitEvent(s1, eConv, 0);
  cudaStreamWaitEvent(s2, eConv, 0);

  // pipelined feat/mlp chunks: stream1 = chunks 0,2 ; stream2 = chunks 1,3
  feat_kernel<<<IDX_PER_CHUNK/256, 256, 0, s1>>>(sino, grid, sq, 0*IDX_PER_CHUNK);
  feat_kernel<<<IDX_PER_CHUNK/256, 256, 0, s2>>>(sino, grid, sq, 1*IDX_PER_CHUNK);
  mlp_mma_kernel<<<TILE_PER_CHUNK, 512, SMEM_MLP, s1>>>(b0, b1, w2, b2, 0*TILE_PER_CHUNK);
  mlp_mma_kernel<<<TILE_PER_CHUNK, 512, SMEM_MLP, s2>>>(b0, b1, w2, b2, 1*TILE_PER_CHUNK);
  feat_kernel<<<IDX_PER_CHUNK/256, 256, 0, s1>>>(sino, grid, sq, 2*IDX_PER_CHUNK);
  feat_kernel<<<IDX_PER_CHUNK/256, 256, 0, s2>>>(sino, grid, sq, 3*IDX_PER_CHUNK);
  mlp_mma_kernel<<<TILE_PER_CHUNK, 512, SMEM_MLP, s1>>>(b0, b1, w2, b2, 2*TILE_PER_CHUNK);
  mlp_mma_kernel<<<TILE_PER_CHUNK, 512, SMEM_MLP, s2>>>(b0, b1, w2, b2, 3*TILE_PER_CHUNK);

  cudaEventRecord(eA, s1);
  cudaEventRecord(eB, s2);
  cudaStreamWaitEvent(0, eA, 0);
  cudaStreamWaitEvent(0, eB, 0);
  reduce_kernel<<<256, 256>>>(out);
}

// round 17
// speedup vs baseline: 1.0620x; 1.0620x over previous
#include <cuda_runtime.h>
#include <cstdint>

#define Bq 2
#define Cq 64
#define Vq 180
#define Dq 384
#define Wq 1024

// ---------------- scratch (device globals) ----------------
__device__ __align__(16) float g_feat[(size_t)Bq*Vq*Dq*96];  // [b][v][d][96]
__device__ __align__(16) float g_X[(size_t)Bq*Vq*Wq*2*64];   // tiles [128pt][64k]
__device__ __align__(16) float g_pred[Bq*Vq*Wq*2];
__device__ __align__(16) float g_coef[Bq*Vq*Wq*2];
__device__ float g_resc[Bq*Vq*Wq];
__device__ __align__(16) unsigned long long g_cwd2[96*640];  // dup weights [oc][c][10] (slot 9 pad)
__device__ float g_cb[96];
__device__ __align__(16) float g_W0t[256*64];     // [h][k], tf32
__device__ __align__(16) float g_W1c[8*256*32];   // [chunk][h][k32], tf32
__device__ float g_cph[32];

// ---------------- helpers ----------------
__device__ __forceinline__ uint32_t smem_u32(const void* p) {
  uint32_t a;
  asm("{ .reg .u64 t; cvta.to.shared.u64 t, %1; cvt.u32.u64 %0, t; }" : "=r"(a) : "l"(p));
  return a;
}
__device__ __forceinline__ float tf32r(float x) {
  uint32_t r;
  asm("cvt.rna.tf32.f32 %0, %1;" : "=r"(r) : "f"(x));
  return __uint_as_float(r);
}
__device__ __forceinline__ unsigned long long pack2(float lo, float hi) {
  unsigned long long d;
  asm("mov.b64 %0, {%1, %2};" : "=l"(d) : "f"(lo), "f"(hi));
  return d;
}
__device__ __forceinline__ unsigned long long ffma2(unsigned long long a,
                                                    unsigned long long b,
                                                    unsigned long long c) {
  unsigned long long d;
  asm("fma.rn.f32x2 %0, %1, %2, %3;" : "=l"(d) : "l"(a), "l"(b), "l"(c));
  return d;
}
__device__ __forceinline__ float2 unpack2(unsigned long long u) {
  float2 f;
  asm("mov.b64 {%0,%1}, %2;" : "=f"(f.x), "=f"(f.y) : "l"(u));
  return f;
}
#define CPA16(d, s) asm volatile("cp.async.ca.shared.global [%0], [%1], 16;" :: "r"(d), "l"(s) : "memory")
#define CPCOMMIT()  asm volatile("cp.async.commit_group;" ::: "memory")
#define CPWAIT(n)   asm volatile("cp.async.wait_group %0;" :: "n"(n) : "memory")

__device__ __forceinline__ void mma_tf32(float* d, const uint32_t* a, const uint32_t* b) {
  asm volatile("mma.sync.aligned.m16n8k8.row.col.f32.tf32.tf32.f32 "
               "{%0,%1,%2,%3}, {%4,%5,%6,%7}, {%8,%9}, {%0,%1,%2,%3};"
               : "+f"(d[0]), "+f"(d[1]), "+f"(d[2]), "+f"(d[3])
               : "r"(a[0]), "r"(a[1]), "r"(a[2]), "r"(a[3]), "r"(b[0]), "r"(b[1]));
}
__device__ __forceinline__ void ldmx4(uint32_t* r, uint32_t addr) {
  asm volatile("ldmatrix.sync.aligned.m8n8.x4.shared.b16 {%0,%1,%2,%3}, [%4];"
               : "=r"(r[0]), "=r"(r[1]), "=r"(r[2]), "=r"(r[3]) : "r"(addr));
}
__device__ __forceinline__ void ldmx2(uint32_t* r, uint32_t addr) {
  asm volatile("ldmatrix.sync.aligned.m8n8.x2.shared.b16 {%0,%1}, [%2];"
               : "=r"(r[0]), "=r"(r[1]) : "r"(addr));
}

// ---------------- prep ----------------
__global__ void prep_kernel(const float* __restrict__ coef_w, const float* __restrict__ coef_b,
                            const float* __restrict__ freq_w, const float* __restrict__ freq_b,
                            const float* __restrict__ phase_w, const void* __restrict__ scale_raw,
                            const float* __restrict__ w0, const float* __restrict__ w1) {
  int t = blockIdx.x * blockDim.x + threadIdx.x;
  if (t < 96*576) {
    int oc = t / 576, j = t % 576;
    int c = j / 9, kk = j % 9;
    float w;
    if (oc < 64) w = coef_w[oc*576 + j];
    else {
      int p = oc - 64;
      w = freq_w[(2*p)*576 + j] + freq_w[(2*p+1)*576 + j];
    }
    g_cwd2[(size_t)oc*640 + c*10 + kk] = pack2(w, w);
  }
  if (t < 96) g_cb[t] = (t < 64) ? coef_b[t] : (freq_b[2*(t-64)] + freq_b[2*(t-64)+1]);
  if (t < 64*256) {
    int k = t >> 8, h = t & 255;
    g_W0t[h*64 + k] = tf32r(w0[k*256 + h]);
  }
  {
    int k = t >> 8, h = t & 255;
    int c = k >> 5, kk = k & 31;
    g_W1c[((size_t)c*256 + h)*32 + kk] = tf32r(w1[k*256 + h]);
  }
  if (t < 32) {
    int raw = *(const int*)scale_raw;
    float sc;
    if (raw > 0 && raw < 1000000) sc = (float)raw;
    else {
      float f = __int_as_float(raw);
      sc = (f > 0.01f && f < 1.0e6f) ? f : 2.0f;
    }
    g_cph[t] = (2.0f / sc) * phase_w[t];
  }
}

// ---------------- conv3x3: vectorized weight loads, P hoisted per channel ----------------
__global__ void __launch_bounds__(96) conv_kernel(const float* __restrict__ sino) {
  extern __shared__ float s_in[];                  // [64][3][66]
  const int b = blockIdx.z, v = blockIdx.y, d0 = blockIdx.x * 64;
  const int tid = threadIdx.x;
  for (int i = tid; i < 64*198; i += 96) {
    int c = i / 198, rem = i % 198, r = rem / 66, col = rem % 66;
    int gv = v - 1 + r, gd = d0 - 1 + col;
    float val = 0.f;
    if (gv >= 0 && gv < Vq && gd >= 0 && gd < Dq)
      val = sino[(((size_t)b*Cq + c)*Vq + gv)*Dq + gd];
    s_in[i] = val;
  }
  __syncthreads();
  const int pos0 = (tid & 7) * 8;
  const int oc0 = (tid >> 3) * 8;
  unsigned long long acc2[8][4];
#pragma unroll
  for (int i = 0; i < 8; i++)
#pragma unroll
    for (int pj = 0; pj < 4; pj++) acc2[i][pj] = 0ull;

  for (int c = 0; c < 64; c++) {
    // hoist all 27 packed input pairs for this channel
    unsigned long long P[27];
#pragma unroll
    for (int ky = 0; ky < 3; ky++) {
      float in[10];
      int base = c*198 + ky*66 + pos0;
#pragma unroll
      for (int q = 0; q < 10; q++) in[q] = s_in[base + q];
#pragma unroll
      for (int m = 0; m < 9; m++) P[ky*9 + m] = pack2(in[m], in[m+1]);
    }
#pragma unroll
    for (int i = 0; i < 8; i++) {
      const unsigned long long* wb = g_cwd2 + (size_t)(oc0+i)*640 + c*10;
      ulonglong2 w01 = *(const ulonglong2*)(wb);
      ulonglong2 w23 = *(const ulonglong2*)(wb + 2);
      ulonglong2 w45 = *(const ulonglong2*)(wb + 4);
      ulonglong2 w67 = *(const ulonglong2*)(wb + 6);
      unsigned long long w8v = wb[8];
      unsigned long long w[9] = {w01.x, w01.y, w23.x, w23.y, w45.x, w45.y, w67.x, w67.y, w8v};
#pragma unroll
      for (int ky = 0; ky < 3; ky++)
#pragma unroll
        for (int pj = 0; pj < 4; pj++) {
          acc2[i][pj] = ffma2(w[ky*3 + 0], P[ky*9 + 2*pj],     acc2[i][pj]);
          acc2[i][pj] = ffma2(w[ky*3 + 1], P[ky*9 + 2*pj + 1], acc2[i][pj]);
          acc2[i][pj] = ffma2(w[ky*3 + 2], P[ky*9 + 2*pj + 2], acc2[i][pj]);
        }
    }
  }
  size_t outbase = (((size_t)b*Vq + v)*Dq + d0 + pos0) * 96;
#pragma unroll
  for (int i = 0; i < 8; i++) {
    float bb = g_cb[oc0+i];
#pragma unroll
    for (int pj = 0; pj < 4; pj++) {
      float2 vv = unpack2(acc2[i][pj]);
      g_feat[outbase + (size_t)(2*pj)*96 + oc0 + i]   = vv.x + bb;
      g_feat[outbase + (size_t)(2*pj+1)*96 + oc0 + i] = vv.y + bb;
    }
  }
}

// ---------------- featurize: coalesced per-point X rows [pt][64k] ----------------
__global__ void __launch_bounds__(256) feat_kernel(const float* __restrict__ sino,
                                                   const float* __restrict__ grid,
                                                   const float* __restrict__ sq) {
  int idx = blockIdx.x * blockDim.x + threadIdx.x;
  if (idx >= Bq*Vq*Wq) return;
  const int b = idx / (Vq*Wq);
  const float gx = grid[(size_t)idx*2], gy = grid[(size_t)idx*2 + 1];
  const float sqv = sq[idx] * 10000.f;

  float ix = fminf(fmaxf(((gx + 1.f)*Dq - 1.f)*0.5f, 0.f), (float)(Dq-1));
  float iy = fminf(fmaxf(((gy + 1.f)*Vq - 1.f)*0.5f, 0.f), (float)(Vq-1));
  float x0f = floorf(ix), y0f = floorf(iy);
  float wx = ix - x0f, wy = iy - y0f;
  int x0 = (int)x0f, y0 = (int)y0f;
  int x1 = min(x0 + 1, Dq-1), y1 = min(y0 + 1, Vq-1);
  const float* mid = sino + ((size_t)b*Cq + 32)*Vq*Dq;
  float v00 = mid[(size_t)y0*Dq + x0], v01 = mid[(size_t)y0*Dq + x1];
  float v10 = mid[(size_t)y1*Dq + x0], v11 = mid[(size_t)y1*Dq + x1];
  float bp = (v00*(1.f-wx) + v01*wx)*(1.f-wy) + (v10*(1.f-wx) + v11*wx)*wy;
  g_resc[idx] = bp * sqv;

  const int yi = min(max((int)rintf(iy), 0), Vq-1);
  float cph[32];
#pragma unroll
  for (int p = 0; p < 32; p++) cph[p] = g_cph[p];

  const float shmag = 1.0f/(float)Dq + 1e-6f;
  float len[2];
#pragma unroll 1
  for (int si = 0; si < 2; si++) {
    float sh = si ? shmag : -shmag;
    float ixs = fminf(fmaxf(((gx + sh + 1.f)*Dq - 1.f)*0.5f, 0.f), (float)(Dq-1));
    int xi = min(max((int)rintf(ixs), 0), Dq-1);
    float qc = (2.f*(float)xi + 1.f)/(float)Dq - 1.f;
    float rel = (gx - qc)*(float)Dq;
    len[si] = fabsf(rel) + 1e-4f;
    const float4* f4 = (const float4*)(g_feat + (((size_t)b*Vq + yi)*Dq + xi)*96);
    float xw[64];
#pragma unroll
    for (int p0 = 0; p0 < 32; p0 += 8) {
      float4 cl0 = f4[p0/4],      cl1 = f4[p0/4 + 1];
      float4 ch0 = f4[8 + p0/4],  ch1 = f4[9 + p0/4];
      float4 fs0 = f4[16 + p0/4], fs1 = f4[17 + p0/4];
      float clo[8] = {cl0.x,cl0.y,cl0.z,cl0.w, cl1.x,cl1.y,cl1.z,cl1.w};
      float chi[8] = {ch0.x,ch0.y,ch0.z,ch0.w, ch1.x,ch1.y,ch1.z,ch1.w};
      float fsv[8] = {fs0.x,fs0.y,fs0.z,fs0.w, fs1.x,fs1.y,fs1.z,fs1.w};
#pragma unroll
      for (int j = 0; j < 8; j++) {
        float fr = fmaf(rel, fsv[j], cph[p0 + j]);
        float sn, cs;
        sincospif(fr, &sn, &cs);
        xw[p0 + j]      = tf32r(clo[j]*cs);
        xw[32 + p0 + j] = tf32r(chi[j]*sn);
      }
    }
    size_t pt = (size_t)idx*2 + si;
    float4* dst = (float4*)(g_X + pt*64);
#pragma unroll
    for (int gq = 0; gq < 16; gq++)
      dst[gq] = make_float4(xw[4*gq], xw[4*gq+1], xw[4*gq+2], xw[4*gq+3]);
  }
  float tot = len[0] + len[1];
  g_coef[idx*2]     = sqv * len[1] / tot;
  g_coef[idx*2 + 1] = sqv * len[0] / tot;
}

// ---------------- MLP via mma.sync tf32 + ldmatrix fragments (proven) ----------------
#define PXT 68
#define PW  68
#define PW1 36
#define H1P 260
#define OFF_W0  8704
#define OFF_BUF 33280
#define BUFSZ   9216
#define SMEM_MLP ((OFF_BUF + 2*BUFSZ) * 4)

__global__ void __launch_bounds__(512, 1) mlp_mma_kernel(const float* __restrict__ b0,
                                                         const float* __restrict__ b1,
                                                         const float* __restrict__ w2,
                                                         const float* __restrict__ b2) {
  extern __shared__ float smem[];
  const uint32_t sbase = smem_u32(smem);
  const int tid = threadIdx.x;
  const int wid = tid >> 5, lane = tid & 31;
  const int g = lane >> 2, tig = lane & 3;
  const int mg = wid & 3;
  const int m0w = mg * 64, n0w = (wid >> 2) * 32;
  const int lr16 = lane & 15;
  const int lr8  = lane & 7;
  const int acol = ((lane >> 4) & 1) * 4;
  const int bcol = ((lane >> 3) & 1) * 4;

  {
    const float* gX = g_X + (size_t)blockIdx.x * 8192;
    for (int i = tid; i < 2048; i += 512) {
      uint32_t d = sbase + (uint32_t)(((i >> 4)*PXT + (i & 15)*4) * 4);
      CPA16(d, gX + i*4);
    }
    for (int i = tid; i < 4096; i += 512) {
      uint32_t d = sbase + (uint32_t)((OFF_W0 + (i >> 4)*PW + (i & 15)*4) * 4);
      CPA16(d, g_W0t + (i >> 4)*64 + (i & 15)*4);
    }
    CPCOMMIT();
    for (int i = tid; i < 2048; i += 512) {
      uint32_t d = sbase + (uint32_t)((OFF_BUF + (i >> 3)*PW1 + (i & 7)*4) * 4);
      CPA16(d, g_W1c + (i >> 3)*32 + (i & 7)*4);
    }
    CPCOMMIT();
    for (int i = tid; i < 2048; i += 512) {
      uint32_t d = sbase + (uint32_t)((OFF_BUF + BUFSZ + (i >> 3)*PW1 + (i & 7)*4) * 4);
      CPA16(d, g_W1c + 8192 + (i >> 3)*32 + (i & 7)*4);
    }
    CPCOMMIT();
  }
  CPWAIT(2);
  __syncthreads();

  float acc0[4][4][4];
#pragma unroll
  for (int mt = 0; mt < 4; mt++)
#pragma unroll
    for (int nt = 0; nt < 4; nt++)
#pragma unroll
      for (int r = 0; r < 4; r++) acc0[mt][nt][r] = 0.f;
  {
    const uint32_t aBase = sbase + (uint32_t)((OFF_W0 + (m0w + lr16)*PW + acol) * 4);
    const uint32_t bBase = sbase + (uint32_t)(((n0w + lr8)*PXT + bcol) * 4);
#pragma unroll
    for (int ks = 0; ks < 8; ks++) {
      const uint32_t koff = (uint32_t)(ks * 32);
      uint32_t Af[4][4], Bf[4][2];
#pragma unroll
      for (int mt = 0; mt < 4; mt++) ldmx4(Af[mt], aBase + (uint32_t)(mt*16*PW*4) + koff);
#pragma unroll
      for (int nt = 0; nt < 4; nt++) ldmx2(Bf[nt], bBase + (uint32_t)(nt*8*PXT*4) + koff);
#pragma unroll
      for (int mt = 0; mt < 4; mt++)
#pragma unroll
        for (int nt = 0; nt < 4; nt++)
          mma_tf32(acc0[mt][nt], Af[mt], Bf[nt]);
    }
  }
  __syncthreads();

#pragma unroll
  for (int mt = 0; mt < 4; mt++) {
    int h_a = m0w + mt*16 + g, h_b = h_a + 8;
    float ba = b0[h_a], bbv = b0[h_b];
#pragma unroll
    for (int nt = 0; nt < 4; nt++) {
      int col = n0w + nt*8 + 2*tig;
      smem[col*H1P + h_a]       = tf32r(fmaxf(acc0[mt][nt][0] + ba, 0.f));
      smem[(col + 1)*H1P + h_a] = tf32r(fmaxf(acc0[mt][nt][1] + ba, 0.f));
      smem[col*H1P + h_b]       = tf32r(fmaxf(acc0[mt][nt][2] + bbv, 0.f));
      smem[(col + 1)*H1P + h_b] = tf32r(fmaxf(acc0[mt][nt][3] + bbv, 0.f));
    }
  }
  CPWAIT(1);
  __syncthreads();

  float acc1[4][4][4];
#pragma unroll
  for (int mt = 0; mt < 4; mt++)
#pragma unroll
    for (int nt = 0; nt < 4; nt++)
#pragma unroll
      for (int r = 0; r < 4; r++) acc1[mt][nt][r] = 0.f;

  const uint32_t bBase1 = sbase + (uint32_t)(((n0w + lr8)*H1P + bcol) * 4);
#pragma unroll 1
  for (int c = 0; c < 8; c++) {
    const int buf = OFF_BUF + (c & 1)*BUFSZ;
    const uint32_t aBase1 = sbase + (uint32_t)((buf + (m0w + lr16)*PW1 + acol) * 4);
    const uint32_t bChunk = bBase1 + (uint32_t)(c*32*4);
#pragma unroll
    for (int ks = 0; ks < 4; ks++) {
      const uint32_t koff = (uint32_t)(ks * 32);
      uint32_t Af[4][4], Bf[4][2];
#pragma unroll
      for (int mt = 0; mt < 4; mt++) ldmx4(Af[mt], aBase1 + (uint32_t)(mt*16*PW1*4) + koff);
#pragma unroll
      for (int nt = 0; nt < 4; nt++) ldmx2(Bf[nt], bChunk + (uint32_t)(nt*8*H1P*4) + koff);
#pragma unroll
      for (int mt = 0; mt < 4; mt++)
#pragma unroll
        for (int nt = 0; nt < 4; nt++)
          mma_tf32(acc1[mt][nt], Af[mt], Bf[nt]);
    }
    __syncthreads();
    if (c + 2 < 8) {
      const float* src = g_W1c + (size_t)(c + 2)*8192;
      for (int i = tid; i < 2048; i += 512) {
        uint32_t d = sbase + (uint32_t)((buf + (i >> 3)*PW1 + (i & 7)*4) * 4);
        CPA16(d, src + (i >> 3)*32 + (i & 7)*4);
      }
      CPCOMMIT();
      CPWAIT(1);
    } else {
      CPWAIT(0);
    }
    __syncthreads();
  }

  float pc[4][2];
#pragma unroll
  for (int nt = 0; nt < 4; nt++) { pc[nt][0] = 0.f; pc[nt][1] = 0.f; }
#pragma unroll
  for (int mt = 0; mt < 4; mt++) {
    int h_a = m0w + mt*16 + g, h_b = h_a + 8;
    float b1a = b1[h_a], w2a = w2[h_a];
    float b1b = b1[h_b], w2b = w2[h_b];
#pragma unroll
    for (int nt = 0; nt < 4; nt++) {
      pc[nt][0] += fmaxf(acc1[mt][nt][0] + b1a, 0.f)*w2a + fmaxf(acc1[mt][nt][2] + b1b, 0.f)*w2b;
      pc[nt][1] += fmaxf(acc1[mt][nt][1] + b1a, 0.f)*w2a + fmaxf(acc1[mt][nt][3] + b1b, 0.f)*w2b;
    }
  }
#pragma unroll
  for (int nt = 0; nt < 4; nt++) {
    int col = n0w + nt*8 + 2*tig;
    smem[OFF_BUF + col*33 + mg*8 + g]       = pc[nt][0];
    smem[OFF_BUF + (col + 1)*33 + mg*8 + g] = pc[nt][1];
  }
  __syncthreads();
  if (tid < 128) {
    float s = b2[0];
#pragma unroll
    for (int j = 0; j < 32; j++) s += smem[OFF_BUF + tid*33 + j];
    g_pred[(size_t)blockIdx.x*128 + tid] = s;
  }
}

// ---------------- final reduce: one warp per output pixel ----------------
__global__ void __launch_bounds__(256) reduce_kernel(float* __restrict__ out) {
  int o = blockIdx.x * 8 + (threadIdx.x >> 5);
  int lane = threadIdx.x & 31;
  int b = o >> 10, w = o & 1023;
  float s = 0.f;
  for (int v = lane; v < Vq; v += 32) {
    size_t idx = ((size_t)b*Vq + v)*Wq + w;
    float2 pr = *(const float2*)&g_pred[idx*2];
    float2 cf = *(const float2*)&g_coef[idx*2];
    s += g_resc[idx] + pr.x*cf.x + pr.y*cf.y;
  }
#pragma unroll
  for (int m = 16; m; m >>= 1) s += __shfl_xor_sync(0xFFFFFFFFu, s, m);
  if (lane == 0) out[o] = s;
}

extern "C" void kernel_launch(void* const* d_in, const int* in_sizes, int n_in,
                              void* d_out, int out_size) {
  const float* sino   = (const float*)d_in[0];
  const float* grid   = (const float*)d_in[1];
  const float* sq     = (const float*)d_in[2];
  const void*  scale  = d_in[3];
  const float* coef_w = (const float*)d_in[4];
  const float* coef_b = (const float*)d_in[5];
  const float* freq_w = (const float*)d_in[6];
  const float* freq_b = (const float*)d_in[7];
  const float* phase_w= (const float*)d_in[8];
  const float* w0     = (const float*)d_in[9];
  const float* b0     = (const float*)d_in[10];
  const float* w1     = (const float*)d_in[11];
  const float* b1     = (const float*)d_in[12];
  const float* w2     = (const float*)d_in[13];
  const float* b2     = (const float*)d_in[14];
  float* out = (float*)d_out;

  static int configured = 0;
  if (!configured) {
    cudaFuncSetAttribute(mlp_mma_kernel, cudaFuncAttributeMaxDynamicSharedMemorySize, SMEM_MLP);
    cudaFuncSetAttribute(conv_kernel,    cudaFuncAttributeMaxDynamicSharedMemorySize, 50688);
    configured = 1;
  }

  prep_kernel<<<256, 256>>>(coef_w, coef_b, freq_w, freq_b, phase_w, scale, w0, w1);
  conv_kernel<<<dim3(Dq/64, Vq, Bq), 96, 50688>>>(sino);
  feat_kernel<<<(Bq*Vq*Wq + 255)/256, 256>>>(sino, grid, sq);
  mlp_mma_kernel<<<Bq*Vq*Wq*2/128, 512, SMEM_MLP>>>(b0, b1, w2, b2);
  reduce_kernel<<<256, 256>>>(out);
}